// round 16
// baseline (speedup 1.0000x reference)
#include <cuda_runtime.h>
#include <cuda_bf16.h>
#include <cstdint>

// Problem constants (match reference)
#define N_B   16
#define T_DIM 4096
#define F_DIM 256
#define PAD_MAX 1228                   // int(0.3 * 4096)
#define TP    (T_DIM + 2 * PAD_MAX)    // 6552

#define OUT_ELEMS (N_B * TP * F_DIM)   // 26,836,992

// Partition 1: source rows (read once, scatter to 1-3 dests)
// Partition 2: zero rows (no reads)
#define ROWS_PER_WARP  2
#define WARPS_PER_BLK  8
#define ROWS_PER_BLK   (ROWS_PER_WARP * WARPS_PER_BLK)            // 16
#define SRC_BLOCKS     (T_DIM / ROWS_PER_BLK)                     // 256 (exact)
#define ZERO_BLOCKS    ((TP + ROWS_PER_BLK - 1) / ROWS_PER_BLK)   // 410
#define GRID_X         (SRC_BLOCKS + ZERO_BLOCKS)                 // 666

// 256-bit non-coherent load with L2 evict-last priority (sm_103 requires
// .v4.b64 for this modifier). Pins the input's 64 MB in L2 across graph
// replays (measured: -20% DRAM traffic) so capacity spill lands on dead
// output lines instead.
__device__ __forceinline__ void ldg256_evict_last(const float* p,
                                                  unsigned long long& r0,
                                                  unsigned long long& r1,
                                                  unsigned long long& r2,
                                                  unsigned long long& r3) {
    asm("ld.global.nc.L2::evict_last.v4.b64 {%0,%1,%2,%3}, [%4];"
        : "=l"(r0), "=l"(r1), "=l"(r2), "=l"(r3) : "l"(p));
}

// 256-bit store: one instruction per lane covers its full contiguous 32 B,
// so a warp stores 1024 B (one row) fully coalesced.
__device__ __forceinline__ void stg256(float* p,
                                       unsigned long long r0, unsigned long long r1,
                                       unsigned long long r2, unsigned long long r3) {
    asm volatile("st.global.v4.b64 [%0], {%1,%2,%3,%4};"
                 :: "l"(p), "l"(r0), "l"(r1), "l"(r2), "l"(r3) : "memory");
}

__global__ __launch_bounds__(256)
void random_shift_kernel(const float* __restrict__ in_,
                         const int*   __restrict__ in_lens,
                         const int*   __restrict__ pad,
                         float* __restrict__ out,
                         int tail_count)
{
    const int n    = blockIdx.y;
    const int w    = threadIdx.x >> 5;
    const int lane = threadIdx.x & 31;

    // warp-uniform metadata (L1 broadcast hits)
    const int lens = __ldg(&in_lens[n]);
    const int p0   = __ldg(&pad[n]);
    const int p1   = __ldg(&pad[N_B + n]);

    float* out_n = out + (size_t)n * TP * F_DIM;
    const int out_len = lens + p0 + p1;

    if (blockIdx.x < SRC_BLOCKS) {
        // ── scatter partition: each src row read ONCE, written to 1-3 dests ──
        // Lane owns 32 B: floats [lane*8, lane*8+8) of the 1 KB row.
        const float* in_n = in_ + (size_t)n * T_DIM * F_DIM;
        const int s0 = blockIdx.x * ROWS_PER_BLK + w * ROWS_PER_WARP;
        const int fo = lane * 8;   // float offset within row

        bool act[ROWS_PER_WARP];
        const float* sp[ROWS_PER_WARP];
        #pragma unroll
        for (int r = 0; r < ROWS_PER_WARP; r++) {
            int s = s0 + r;
            act[r] = (s < lens);
            sp[r]  = in_n + (size_t)s * F_DIM + fo;
        }

        // 256-bit evict-last loads: input pinned L2-resident across replays
        unsigned long long v[ROWS_PER_WARP][4];
        #pragma unroll
        for (int r = 0; r < ROWS_PER_WARP; r++) {
            if (act[r]) {
                ldg256_evict_last(sp[r], v[r][0], v[r][1], v[r][2], v[r][3]);
            } else {
                v[r][0] = v[r][1] = v[r][2] = v[r][3] = 0ull;
            }
        }

        #pragma unroll
        for (int r = 0; r < ROWS_PER_WARP; r++) {
            if (!act[r]) continue;
            int s = s0 + r;

            // mid: t = p0 + s  (always valid)
            stg256(out_n + (size_t)(p0 + s) * F_DIM + fo,
                   v[r][0], v[r][1], v[r][2], v[r][3]);
            // left reflect: t = p0 - s, valid for 1 <= s <= p0
            if (s >= 1 && s <= p0) {
                stg256(out_n + (size_t)(p0 - s) * F_DIM + fo,
                       v[r][0], v[r][1], v[r][2], v[r][3]);
            }
            // right reflect: t = 2*lens + p0 - 2 - s, valid for lens-p1-1 <= s <= lens-2
            if (s >= lens - p1 - 1 && s <= lens - 2) {
                stg256(out_n + (size_t)(2 * lens + p0 - 2 - s) * F_DIM + fo,
                       v[r][0], v[r][1], v[r][2], v[r][3]);
            }
        }
    } else {
        // ── zero partition: t in [out_len, TP) ──
        const int t0 = (blockIdx.x - SRC_BLOCKS) * ROWS_PER_BLK + w * ROWS_PER_WARP;
        const int fo = lane * 8;
        #pragma unroll
        for (int r = 0; r < ROWS_PER_WARP; r++) {
            int t = t0 + r;
            if (t < TP && t >= out_len) {
                stg256(out_n + (size_t)t * F_DIM + fo, 0ull, 0ull, 0ull, 0ull);
            }
        }
    }

    // Fold out_lens tail write into the first block (values exact in fp32).
    if (blockIdx.x == 0 && blockIdx.y == 0 && threadIdx.x < 16) {
        int ix = threadIdx.x;
        if (ix < tail_count) {
            int ol = __ldg(&in_lens[ix]) + __ldg(&pad[ix]) + __ldg(&pad[N_B + ix]);
            out[OUT_ELEMS + ix] = (float)ol;
        }
    }
}

extern "C" void kernel_launch(void* const* d_in, const int* in_sizes, int n_in,
                              void* d_out, int out_size)
{
    const float* in_  = (const float*)d_in[0];
    const int*   lens = (const int*)d_in[1];
    const int*   pad  = (const int*)d_in[2];
    float*       out  = (float*)d_out;

    int tail = out_size - OUT_ELEMS;   // out_lens packed after main tensor (if present)
    if (tail < 0) tail = 0;

    dim3 grid(GRID_X, N_B, 1);         // 666 x 16 = 10656 blocks
    random_shift_kernel<<<grid, 256>>>(in_, lens, pad, out, tail);
}

// round 17
// speedup vs baseline: 1.1444x; 1.1444x over previous
#include <cuda_runtime.h>
#include <cuda_bf16.h>
#include <cstdint>

// Problem constants (match reference)
#define N_B   16
#define T_DIM 4096
#define F_DIM 256
#define PAD_MAX 1228                   // int(0.3 * 4096)
#define TP    (T_DIM + 2 * PAD_MAX)    // 6552

#define OUT_ELEMS (N_B * TP * F_DIM)   // 26,836,992

// Partition 1: source rows (read once, scatter to 1-3 dests)
// Partition 2: zero rows (no reads)
#define ROWS_PER_WARP  2
#define WARPS_PER_BLK  8
#define ROWS_PER_BLK   (ROWS_PER_WARP * WARPS_PER_BLK)            // 16
#define SRC_BLOCKS     (T_DIM / ROWS_PER_BLK)                     // 256 (exact)
#define ZERO_BLOCKS    ((TP + ROWS_PER_BLK - 1) / ROWS_PER_BLK)   // 410
#define GRID_X         (SRC_BLOCKS + ZERO_BLOCKS)                 // 666

__global__ __launch_bounds__(256)
void random_shift_kernel(const float* __restrict__ in_,
                         const int*   __restrict__ in_lens,
                         const int*   __restrict__ pad,
                         float* __restrict__ out,
                         int tail_count)
{
    const int n    = blockIdx.y;
    const int w    = threadIdx.x >> 5;
    const int lane = threadIdx.x & 31;

    // warp-uniform metadata (L1 broadcast hits)
    const int lens = __ldg(&in_lens[n]);
    const int p0   = __ldg(&pad[n]);
    const int p1   = __ldg(&pad[N_B + n]);

    float* out_n = out + (size_t)n * TP * F_DIM;
    const int out_len = lens + p0 + p1;

    if (blockIdx.x < SRC_BLOCKS) {
        // ── scatter partition: each src row read ONCE, written to 1-3 dests ──
        const float* in_n = in_ + (size_t)n * T_DIM * F_DIM;
        const int s0 = blockIdx.x * ROWS_PER_BLK + w * ROWS_PER_WARP;

        bool act[ROWS_PER_WARP];
        const float4* sp[ROWS_PER_WARP];
        #pragma unroll
        for (int r = 0; r < ROWS_PER_WARP; r++) {
            int s = s0 + r;
            act[r] = (s < lens);
            sp[r]  = reinterpret_cast<const float4*>(in_n + (size_t)s * F_DIM) + lane;
        }

        // cached loads: input stays L2-resident across graph replays
        float4 val[ROWS_PER_WARP][2];
        #pragma unroll
        for (int r = 0; r < ROWS_PER_WARP; r++) {
            #pragma unroll
            for (int h = 0; h < 2; h++) {
                val[r][h] = act[r] ? __ldg(sp[r] + h * 32)
                                   : make_float4(0.f, 0.f, 0.f, 0.f);
            }
        }

        #pragma unroll
        for (int r = 0; r < ROWS_PER_WARP; r++) {
            if (!act[r]) continue;
            int s = s0 + r;

            // mid: t = p0 + s  (always valid)
            {
                float4* op = reinterpret_cast<float4*>(out_n + (size_t)(p0 + s) * F_DIM) + lane;
                __stcs(op,      val[r][0]);
                __stcs(op + 32, val[r][1]);
            }
            // left reflect: t = p0 - s, valid for 1 <= s <= p0
            if (s >= 1 && s <= p0) {
                float4* op = reinterpret_cast<float4*>(out_n + (size_t)(p0 - s) * F_DIM) + lane;
                __stcs(op,      val[r][0]);
                __stcs(op + 32, val[r][1]);
            }
            // right reflect: t = 2*lens + p0 - 2 - s, valid for lens-p1-1 <= s <= lens-2
            if (s >= lens - p1 - 1 && s <= lens - 2) {
                float4* op = reinterpret_cast<float4*>(out_n + (size_t)(2 * lens + p0 - 2 - s) * F_DIM) + lane;
                __stcs(op,      val[r][0]);
                __stcs(op + 32, val[r][1]);
            }
        }
    } else {
        // ── zero partition: t in [out_len, TP) ──
        const int t0 = (blockIdx.x - SRC_BLOCKS) * ROWS_PER_BLK + w * ROWS_PER_WARP;
        const float4 z = make_float4(0.f, 0.f, 0.f, 0.f);
        #pragma unroll
        for (int r = 0; r < ROWS_PER_WARP; r++) {
            int t = t0 + r;
            if (t < TP && t >= out_len) {
                float4* op = reinterpret_cast<float4*>(out_n + (size_t)t * F_DIM) + lane;
                __stcs(op,      z);
                __stcs(op + 32, z);
            }
        }
    }

    // Fold out_lens tail write into the first block (values exact in fp32).
    if (blockIdx.x == 0 && blockIdx.y == 0 && threadIdx.x < 16) {
        int ix = threadIdx.x;
        if (ix < tail_count) {
            int ol = __ldg(&in_lens[ix]) + __ldg(&pad[ix]) + __ldg(&pad[N_B + ix]);
            out[OUT_ELEMS + ix] = (float)ol;
        }
    }
}

extern "C" void kernel_launch(void* const* d_in, const int* in_sizes, int n_in,
                              void* d_out, int out_size)
{
    const float* in_  = (const float*)d_in[0];
    const int*   lens = (const int*)d_in[1];
    const int*   pad  = (const int*)d_in[2];
    float*       out  = (float*)d_out;

    int tail = out_size - OUT_ELEMS;   // out_lens packed after main tensor (if present)
    if (tail < 0) tail = 0;

    dim3 grid(GRID_X, N_B, 1);         // 666 x 16 = 10656 blocks
    random_shift_kernel<<<grid, 256>>>(in_, lens, pad, out, tail);
}